// round 1
// baseline (speedup 1.0000x reference)
#include <cuda_runtime.h>
#include <math.h>

// Problem constants: B=32, N=160, C=3, L=128
// SSIM: VALID 11x11 gaussian -> 150x150 output
// STFT: f=12, s=4 -> p=38 patches per dim, keep bins u,v in 1..5 (weight u*v/25)

#define SSIM_BLOCKS (50*96)   // 5 x 10 tiles x (32 b * 3 c) = 4800
#define STFT_BLOCKS (38*32)   // patch rows x batch = 1216

__device__ float g_ssim[SSIM_BLOCKS];
__device__ float g_stft[STFT_BLOCKS];

// ---------------------------------------------------------------------------
// SSIM kernel: separable gaussian, 32x16 output tile per block, 512 threads.
// ---------------------------------------------------------------------------
__global__ void __launch_bounds__(512) ssim_kernel(const float* __restrict__ xin,
                                                   const float* __restrict__ xout)
{
    __shared__ float sx[26][42];
    __shared__ float sy[26][42];
    __shared__ float h5[5][26][32];
    __shared__ float red[512];

    // gn[i] = g[i]/sum(g), g[i]=exp(-0.5*((i-5)/1.5)^2)  (compile-time literals!)
    const float GN[11] = {0.00102838f, 0.00759887f, 0.03600077f, 0.10936069f,
                          0.21300553f, 0.26601172f, 0.21300553f, 0.10936069f,
                          0.03600077f, 0.00759887f, 0.00102838f};

    const int bz = blockIdx.z;           // b*3 + c
    const int c  = bz % 3, b = bz / 3;
    const int ox = blockIdx.x * 32, oy = blockIdx.y * 16;
    const int tid = threadIdx.x;

    const float* pin  = xin  + (size_t)b * (160*160*3) + c;
    const float* pout = xout + (size_t)b * (160*160*3) + c;

    // load input tile (with halo), zero-pad out of range (masked outputs anyway)
    for (int i = tid; i < 26*42; i += 512) {
        int r = i / 42, cc = i - r*42;
        int gr = oy + r, gc = ox + cc;
        float vx = 0.f, vy = 0.f;
        if (gr < 160 && gc < 160) {
            size_t off = ((size_t)gr*160 + gc) * 3;
            vx = pin[off]; vy = pout[off];
        }
        sx[r][cc] = vx; sy[r][cc] = vy;
    }
    __syncthreads();

    // horizontal pass: 5 fused moment fields
    for (int i = tid; i < 26*32; i += 512) {
        int r = i >> 5, cc = i & 31;
        float hx=0.f, hy=0.f, hxx=0.f, hyy=0.f, hxy=0.f;
        #pragma unroll
        for (int k = 0; k < 11; k++) {
            float w = GN[k];
            float a = sx[r][cc+k], d = sy[r][cc+k];
            hx += w*a; hy += w*d;
            hxx += w*a*a; hyy += w*d*d; hxy += w*a*d;
        }
        h5[0][r][cc]=hx; h5[1][r][cc]=hy; h5[2][r][cc]=hxx;
        h5[3][r][cc]=hyy; h5[4][r][cc]=hxy;
    }
    __syncthreads();

    // vertical pass + SSIM formula
    float val = 0.f;
    {
        int tx = tid & 31, ty = tid >> 5;
        int gx = ox + tx, gy = oy + ty;
        if (gx < 150 && gy < 150) {
            float mx=0.f, my=0.f, exx=0.f, eyy=0.f, exy=0.f;
            #pragma unroll
            for (int k = 0; k < 11; k++) {
                float w = GN[k];
                mx  += w*h5[0][ty+k][tx];
                my  += w*h5[1][ty+k][tx];
                exx += w*h5[2][ty+k][tx];
                eyy += w*h5[3][ty+k][tx];
                exy += w*h5[4][ty+k][tx];
            }
            const float C1 = 1e-4f, C2 = 9e-4f;
            float vx  = exx - mx*mx;
            float vy  = eyy - my*my;
            float cov = exy - mx*my;
            float lum = (2.f*mx*my + C1) / (mx*mx + my*my + C1);
            float cs  = (2.f*cov + C2) / (vx + vy + C2);
            val = lum * cs;
        }
    }

    red[tid] = val;
    __syncthreads();
    #pragma unroll
    for (int s = 256; s > 0; s >>= 1) {
        if (tid < s) red[tid] += red[tid + s];
        __syncthreads();
    }
    if (tid == 0)
        g_ssim[(size_t)bz*50 + blockIdx.y*5 + blockIdx.x] = red[0];
}

// ---------------------------------------------------------------------------
// STFT kernel: block = (patch_row, batch). Loads 12 image rows (full width,
// all channels, both images) to smem once; each of 114 threads handles one
// (patch, channel) item: direct 12-pt DFT, bins u,v in 1..5, weight u*v/25.
// Smem swizzled (+i/32) to kill the stride-4 4-way bank conflict.
// ---------------------------------------------------------------------------
__global__ void __launch_bounds__(128) stft_kernel(const float* __restrict__ xin,
                                                   const float* __restrict__ xout)
{
    __shared__ float sIn[12][495];
    __shared__ float sOut[12][495];
    __shared__ float red[128];

    const int b = blockIdx.y;
    const int prow = blockIdx.x;   // 0..37, image rows prow*4 .. prow*4+11
    const int tid = threadIdx.x;

    const size_t gbase = ((size_t)b * 160 + (size_t)prow * 4) * 480;
    for (int t = tid; t < 12*480; t += 128) {
        int y = t / 480, q = t - y*480;
        int qs = q + (q >> 5);               // swizzle pad
        sIn[y][qs]  = xin [gbase + (size_t)y*480 + q];
        sOut[y][qs] = xout[gbase + (size_t)y*480 + q];
    }
    __syncthreads();

    float acc = 0.f;
    if (tid < 114) {
        const int j = tid / 3;               // patch column 0..37
        const int c = tid - 3*j;             // channel

        // twiddles cos/sin(2*pi*k/12) — become immediates after full unroll
        const float CT[12] = { 1.f, 0.8660254038f, 0.5f, 0.f, -0.5f, -0.8660254038f,
                              -1.f,-0.8660254038f,-0.5f, 0.f,  0.5f,  0.8660254038f};
        const float ST[12] = { 0.f, 0.5f, 0.8660254038f, 1.f, 0.8660254038f, 0.5f,
                               0.f,-0.5f,-0.8660254038f,-1.f,-0.8660254038f,-0.5f};

        float Air[25], Aii[25], Aor[25], Aoi[25];
        #pragma unroll
        for (int i = 0; i < 25; i++) { Air[i]=0.f; Aii[i]=0.f; Aor[i]=0.f; Aoi[i]=0.f; }

        const int cbase = 12*j + c;          // (4j + x)*3 + c  at x=0

        #pragma unroll
        for (int x = 0; x < 12; x++) {
            const int col = cbase + 3*x;
            const int cs  = col + (col >> 5);
            float ci[12], co[12];
            #pragma unroll
            for (int y = 0; y < 12; y++) { ci[y] = sIn[y][cs]; co[y] = sOut[y][cs]; }

            #pragma unroll
            for (int u = 1; u <= 5; u++) {
                // h[u] = sum_y col[y] * exp(-2*pi*i*u*y/12)
                float hir=0.f, hii=0.f, hor=0.f, hoi=0.f;
                #pragma unroll
                for (int y = 0; y < 12; y++) {
                    const float cw = CT[(u*y) % 12];
                    const float swv = ST[(u*y) % 12];
                    hir += ci[y]*cw; hii -= ci[y]*swv;
                    hor += co[y]*cw; hoi -= co[y]*swv;
                }
                #pragma unroll
                for (int v = 1; v <= 5; v++) {
                    const float cw = CT[(v*x) % 12];
                    const float swv = ST[(v*x) % 12];
                    const int idx = (u-1)*5 + (v-1);
                    // F += h * (cw - i*swv)
                    Air[idx] += hir*cw + hii*swv;
                    Aii[idx] += hii*cw - hir*swv;
                    Aor[idx] += hor*cw + hoi*swv;
                    Aoi[idx] += hoi*cw - hor*swv;
                }
            }
        }

        #pragma unroll
        for (int u = 1; u <= 5; u++) {
            #pragma unroll
            for (int v = 1; v <= 5; v++) {
                const int idx = (u-1)*5 + (v-1);
                float ai = atan2f(Aii[idx], Air[idx] + 1e-8f);
                float ao = atan2f(Aoi[idx], Aor[idx] + 1e-8f);
                float mi = sqrtf(Air[idx]*Air[idx] + Aii[idx]*Aii[idx]);
                float mo = sqrtf(Aor[idx]*Aor[idx] + Aoi[idx]*Aoi[idx]);
                acc += (float)(u*v) * (fabsf(ao - ai) + fabsf(mo - mi));
            }
        }
        acc *= (1.f / 25.f);   // ff = (u/5)*(v/5)
    }

    red[tid] = acc;
    __syncthreads();
    #pragma unroll
    for (int s = 64; s > 0; s >>= 1) {
        if (tid < s) red[tid] += red[tid + s];
        __syncthreads();
    }
    if (tid == 0)
        g_stft[blockIdx.y*38 + blockIdx.x] = red[0];
}

// ---------------------------------------------------------------------------
// Final kernel: deterministic fixed-order reduction (fp64 accumulate):
// loss = mean_b( -0.5*sum(1+lv-e^lv-m^2) + ssim_mean + 1e-4*stft_sum )
// ---------------------------------------------------------------------------
__global__ void __launch_bounds__(256) final_kernel(const float* __restrict__ mean,
                                                    const float* __restrict__ logvar,
                                                    float* __restrict__ out)
{
    __shared__ double red[256];
    const int tid = threadIdx.x;
    double acc = 0.0;

    const double K_KLD  = -0.5 / 32.0;
    const double K_SSIM = 1.0 / (32.0 * 150.0 * 150.0 * 3.0);
    const double K_STFT = 1e-4 / 32.0;

    for (int i = tid; i < 32*128; i += 256) {
        float lv = logvar[i], m = mean[i];
        acc += (double)(1.0f + lv - expf(lv) - m*m) * K_KLD;
    }
    for (int i = tid; i < SSIM_BLOCKS; i += 256)
        acc += (double)g_ssim[i] * K_SSIM;
    for (int i = tid; i < STFT_BLOCKS; i += 256)
        acc += (double)g_stft[i] * K_STFT;

    red[tid] = acc;
    __syncthreads();
    #pragma unroll
    for (int s = 128; s > 0; s >>= 1) {
        if (tid < s) red[tid] += red[tid + s];
        __syncthreads();
    }
    if (tid == 0) out[0] = (float)red[0];
}

// ---------------------------------------------------------------------------
extern "C" void kernel_launch(void* const* d_in, const int* in_sizes, int n_in,
                              void* d_out, int out_size)
{
    const float* mean   = (const float*)d_in[0];
    const float* logvar = (const float*)d_in[1];
    const float* xin    = (const float*)d_in[2];
    const float* xout   = (const float*)d_in[3];
    float* out = (float*)d_out;

    ssim_kernel<<<dim3(5, 10, 96), 512>>>(xin, xout);
    stft_kernel<<<dim3(38, 32), 128>>>(xin, xout);
    final_kernel<<<1, 256>>>(mean, logvar, out);
}

// round 2
// speedup vs baseline: 1.8869x; 1.8869x over previous
#include <cuda_runtime.h>
#include <math.h>

// Problem constants: B=32, N=160, C=3, L=128
// SSIM: VALID 11x11 gaussian -> 150x150 output
// STFT: f=12, s=4 -> p=38 patches/dim, bins u,v in 1..5, weight u*v/25

#define SSIM_BLOCKS (5*5*96)   // 25 tiles x (32 b * 3 c) = 2400
#define STFT_BLOCKS (38*32)    // patch rows x batch = 1216

__device__ float g_ssim[SSIM_BLOCKS];
__device__ float g_stft[STFT_BLOCKS];

// gaussian weights (normalized), compile-time immediates
__device__ __forceinline__ constexpr float GNW(int k) {
    constexpr float g[11] = {0.00102838f, 0.00759887f, 0.03600077f, 0.10936069f,
                             0.21300553f, 0.26601172f, 0.21300553f, 0.10936069f,
                             0.03600077f, 0.00759887f, 0.00102838f};
    return g[k];
}

// ---------------------------------------------------------------------------
// SSIM kernel: separable gaussian. 32x32 output tile, 256 threads,
// vertical pass: k-outer / 4-outputs-inner (each h5 row read ONCE).
// ---------------------------------------------------------------------------
__global__ void __launch_bounds__(256) ssim_kernel(const float* __restrict__ xin,
                                                   const float* __restrict__ xout)
{
    __shared__ float sx[42][44];
    __shared__ float sy[42][44];
    __shared__ float h0[42][33], h1[42][33], h2[42][33], h3[42][33], h4s[42][33];
    __shared__ float red[256];

    const int bz = blockIdx.z;           // b*3 + c
    const int c  = bz % 3, b = bz / 3;
    const int ox = blockIdx.x * 32, oy = blockIdx.y * 32;
    const int tid = threadIdx.x;

    const float* pin  = xin  + (size_t)b * (160*160*3) + c;
    const float* pout = xout + (size_t)b * (160*160*3) + c;

    // load 42x42 input tile (halo), zero-pad OOB (those outputs masked)
    for (int i = tid; i < 42*42; i += 256) {
        int r = i / 42, cc = i - r*42;
        int gr = oy + r, gc = ox + cc;
        float vx = 0.f, vy = 0.f;
        if (gr < 160 && gc < 160) {
            size_t off = ((size_t)gr*160 + gc) * 3;
            vx = pin[off]; vy = pout[off];
        }
        sx[r][cc] = vx; sy[r][cc] = vy;
    }
    __syncthreads();

    // horizontal pass: 42 rows x 32 cols of 5 fused moment fields
    for (int i = tid; i < 42*32; i += 256) {
        int r = i >> 5, cc = i & 31;
        float hx=0.f, hy=0.f, hxx=0.f, hyy=0.f, hxy=0.f;
        #pragma unroll
        for (int k = 0; k < 11; k++) {
            float a = sx[r][cc+k], d = sy[r][cc+k];
            float wa = GNW(k)*a, wd = GNW(k)*d;
            hx += wa; hy += wd;
            hxx = fmaf(wa, a, hxx);
            hyy = fmaf(wd, d, hyy);
            hxy = fmaf(wa, d, hxy);
        }
        h0[r][cc]=hx; h1[r][cc]=hy; h2[r][cc]=hxx; h3[r][cc]=hyy; h4s[r][cc]=hxy;
    }
    __syncthreads();

    // vertical pass: 32 cols x 8 row-groups, 4 outputs per thread.
    // k-outer: each h-row read once, feeds up to 4 outputs.
    const int tx = tid & 31, ty = tid >> 5;
    const int rb = ty * 4;

    float a0[4], a1[4], a2[4], a3[4], a4[4];
    #pragma unroll
    for (int g = 0; g < 4; g++) { a0[g]=0.f; a1[g]=0.f; a2[g]=0.f; a3[g]=0.f; a4[g]=0.f; }

    #pragma unroll
    for (int k = 0; k < 14; k++) {
        float t0 = h0[rb+k][tx], t1 = h1[rb+k][tx], t2 = h2[rb+k][tx],
              t3 = h3[rb+k][tx], t4 = h4s[rb+k][tx];
        #pragma unroll
        for (int g = 0; g < 4; g++) {
            const int kk = k - g;
            if (kk >= 0 && kk < 11) {
                a0[g] = fmaf(GNW(kk), t0, a0[g]);
                a1[g] = fmaf(GNW(kk), t1, a1[g]);
                a2[g] = fmaf(GNW(kk), t2, a2[g]);
                a3[g] = fmaf(GNW(kk), t3, a3[g]);
                a4[g] = fmaf(GNW(kk), t4, a4[g]);
            }
        }
    }

    float val = 0.f;
    const int gx = ox + tx;
    #pragma unroll
    for (int g = 0; g < 4; g++) {
        int gy = oy + rb + g;
        if (gx < 150 && gy < 150) {
            const float C1 = 1e-4f, C2 = 9e-4f;
            float mx = a0[g], my = a1[g];
            float vx  = a2[g] - mx*mx;
            float vy  = a3[g] - my*my;
            float cov = a4[g] - mx*my;
            float lum = (2.f*mx*my + C1) / (mx*mx + my*my + C1);
            float cs  = (2.f*cov + C2) / (vx + vy + C2);
            val += lum * cs;
        }
    }

    red[tid] = val;
    __syncthreads();
    #pragma unroll
    for (int s = 128; s > 0; s >>= 1) {
        if (tid < s) red[tid] += red[tid + s];
        __syncthreads();
    }
    if (tid == 0)
        g_ssim[(size_t)bz*25 + blockIdx.y*5 + blockIdx.x] = red[0];
}

// ---------------------------------------------------------------------------
// STFT helpers
// ---------------------------------------------------------------------------
__device__ __forceinline__ constexpr float cw12(int k) {
    constexpr float t[12] = { 1.f, 0.86602540378f, 0.5f, 0.f, -0.5f, -0.86602540378f,
                             -1.f,-0.86602540378f,-0.5f, 0.f,  0.5f,  0.86602540378f};
    return t[k];
}
__device__ __forceinline__ constexpr float sw12(int k) {
    constexpr float t[12] = { 0.f, 0.5f, 0.86602540378f, 1.f, 0.86602540378f, 0.5f,
                              0.f,-0.5f,-0.86602540378f,-1.f,-0.86602540378f,-0.5f};
    return t[k];
}

// 12-point real-input DFT, bins u=1..5, hand-factored (~55 ops)
__device__ __forceinline__ void dft12_5(const float* __restrict__ v,
                                        float* __restrict__ hr,
                                        float* __restrict__ hi)
{
    const float S3 = 0.86602540378f;
    float A1 = v[1]-v[5]-v[7]+v[11];
    float B1 = v[2]-v[4]-v[8]+v[10];
    float D1 = v[0]-v[6];
    float A2 = v[1]+v[5]-v[7]-v[11];
    float B2 = v[2]+v[4]-v[8]-v[10];
    float D2 = v[3]-v[9];
    float t1 = S3*A1, t2 = 0.5f*B1;
    float s1 = 0.5f*A2, s2 = S3*B2;
    hr[0] = D1 + t1 + t2;            hi[0] = -(s1 + s2 + D2);   // u=1
    hr[4] = D1 - t1 + t2;            hi[4] = -(s1 - s2 + D2);   // u=5
    float p0 = v[0]+v[6], p3 = v[3]+v[9];
    float q1 = v[1]+v[7], q2 = v[2]+v[8], q4 = v[4]+v[10], q5 = v[5]+v[11];
    hr[1] = (p0 - p3) + 0.5f*((q1+q5) - (q2+q4));               // u=2
    hi[1] = -S3*((q1+q2) - (q4+q5));
    hr[2] = (v[0]+v[4]+v[8]) - (v[2]+v[6]+v[10]);               // u=3
    hi[2] = (v[3]+v[7]+v[11]) - (v[1]+v[5]+v[9]);
    float E0 = p0+p3, E1 = q1+q4, E2 = q2+q5;
    hr[3] = E0 - 0.5f*(E1+E2);                                  // u=4
    hi[3] = -S3*(E1-E2);
}

__device__ __forceinline__ float fast_atan2f(float y, float x) {
    float ax = fabsf(x), ay = fabsf(y);
    float mx = fmaxf(ax, ay), mn = fminf(ax, ay);
    float t = __fdividef(mn, mx);
    float s = t*t;
    float p =             -0.01172120f;
    p = fmaf(p, s,         0.05265332f);
    p = fmaf(p, s,        -0.11643287f);
    p = fmaf(p, s,         0.19354346f);
    p = fmaf(p, s,        -0.33262347f);
    p = fmaf(p, s,         0.99997726f);
    float r = p * t;
    if (ay > ax)  r = 1.57079632679f - r;
    if (x < 0.f)  r = 3.14159265359f - r;
    return copysignf(r, y);
}

// ---------------------------------------------------------------------------
// STFT kernel: block = (patch_row, batch), 192 threads.
// Phase A: 12-pt column DFT (bins 1..5) ONCE per absolute column (480 cols,
//          both images) -> smem H (swizzled float4).
// Phase B: per (patch j, channel c, bin-row u): 12-pt DFT over x for bins
//          v=1..5, compile-time-folded twiddles; fast epilogue.
// ---------------------------------------------------------------------------
__global__ void __launch_bounds__(192) stft_kernel(const float* __restrict__ xin,
                                                   const float* __restrict__ xout)
{
    __shared__ float4 H[5][540];          // [u][swizzled col] = (hir,hii,hor,hoi)
    __shared__ float red[256];

    const int b = blockIdx.y;
    const int prow = blockIdx.x;          // image rows prow*4 .. prow*4+11
    const int tid = threadIdx.x;

    const float* pin  = xin  + ((long)b * 160 + (long)prow * 4) * 480;
    const float* pout = xout + ((long)b * 160 + (long)prow * 4) * 480;

    // ---- Phase A: column DFTs straight from gmem (coalesced across lanes) ----
    for (int e = tid; e < 480; e += 192) {
        float vi[12], vo[12];
        #pragma unroll
        for (int y = 0; y < 12; y++) {
            vi[y] = pin [y*480 + e];
            vo[y] = pout[y*480 + e];
        }
        float hir[5], hii[5], hor[5], hoi[5];
        dft12_5(vi, hir, hii);
        dft12_5(vo, hor, hoi);
        const int es = e + (e >> 3);      // bank swizzle
        #pragma unroll
        for (int u = 0; u < 5; u++)
            H[u][es] = make_float4(hir[u], hii[u], hor[u], hoi[u]);
    }
    __syncthreads();

    // ---- Phase B: 570 items = 38 patches x 3 ch x 5 u ----
    float acc = 0.f;
    for (int id = tid; id < 570; id += 192) {
        const int u = id / 114;           // 0..4  (bin u+1)
        const int m = id - u*114;         // 0..113 = j*3 + c
        const int cch = m % 3;
        const int ebase = 4*m - 3*cch;    // = 12j + c

        float Fir[5], Fii[5], For[5], Foi[5];
        #pragma unroll
        for (int v = 0; v < 5; v++) { Fir[v]=0.f; Fii[v]=0.f; For[v]=0.f; Foi[v]=0.f; }

        #pragma unroll
        for (int x = 0; x < 12; x++) {
            const int e = ebase + 3*x;
            const int es = e + (e >> 3);
            const float4 h = H[u][es];
            #pragma unroll
            for (int v = 1; v <= 5; v++) {
                const int k = (v*x) % 12;
                const float c_ = cw12(k), s_ = sw12(k);
                const int vi = v - 1;
                if (s_ == 0.f) {                 // tw = +/-1
                    if (c_ > 0.f) { Fir[vi]+=h.x; Fii[vi]+=h.y; For[vi]+=h.z; Foi[vi]+=h.w; }
                    else          { Fir[vi]-=h.x; Fii[vi]-=h.y; For[vi]-=h.z; Foi[vi]-=h.w; }
                } else if (c_ == 0.f) {          // tw = -/+ i
                    if (s_ > 0.f) { Fir[vi]+=h.y; Fii[vi]-=h.x; For[vi]+=h.w; Foi[vi]-=h.z; }
                    else          { Fir[vi]-=h.y; Fii[vi]+=h.x; For[vi]-=h.w; Foi[vi]+=h.z; }
                } else {                         // full cmul (imm-form FMAs)
                    Fir[vi] = fmaf(h.x,  c_, fmaf(h.y,  s_, Fir[vi]));
                    Fii[vi] = fmaf(h.y,  c_, fmaf(h.x, -s_, Fii[vi]));
                    For[vi] = fmaf(h.z,  c_, fmaf(h.w,  s_, For[vi]));
                    Foi[vi] = fmaf(h.w,  c_, fmaf(h.z, -s_, Foi[vi]));
                }
            }
        }

        // epilogue: arg + amp differences, weight u*v/25
        const float wu = (float)(u + 1) * (1.f / 25.f);
        #pragma unroll
        for (int v = 1; v <= 5; v++) {
            const int vi = v - 1;
            float angi = fast_atan2f(Fii[vi], Fir[vi] + 1e-8f);
            float ango = fast_atan2f(Foi[vi], For[vi] + 1e-8f);
            float m2i = fmaf(Fir[vi], Fir[vi], Fii[vi]*Fii[vi]);
            float m2o = fmaf(For[vi], For[vi], Foi[vi]*Foi[vi]);
            float magi = m2i * __frsqrt_rn(fmaxf(m2i, 1e-30f));
            float mago = m2o * __frsqrt_rn(fmaxf(m2o, 1e-30f));
            acc = fmaf((float)v * wu, fabsf(ango - angi) + fabsf(mago - magi), acc);
        }
    }

    red[tid] = acc;
    if (tid < 64) red[tid + 192] = 0.f;   // pad to 256
    __syncthreads();
    #pragma unroll
    for (int s = 128; s > 0; s >>= 1) {
        if (tid < s) red[tid] += red[tid + s];
        __syncthreads();
    }
    if (tid == 0)
        g_stft[blockIdx.y*38 + blockIdx.x] = red[0];
}

// ---------------------------------------------------------------------------
// Final kernel: deterministic fixed-order fp64 reduction.
// loss = mean_b( -0.5*sum(1+lv-e^lv-m^2) + ssim_mean + 1e-4*stft_sum )
// ---------------------------------------------------------------------------
__global__ void __launch_bounds__(256) final_kernel(const float* __restrict__ mean,
                                                    const float* __restrict__ logvar,
                                                    float* __restrict__ out)
{
    __shared__ double red[256];
    const int tid = threadIdx.x;
    double acc = 0.0;

    const double K_KLD  = -0.5 / 32.0;
    const double K_SSIM = 1.0 / (32.0 * 150.0 * 150.0 * 3.0);
    const double K_STFT = 1e-4 / 32.0;

    for (int i = tid; i < 32*128; i += 256) {
        float lv = logvar[i], m = mean[i];
        acc += (double)(1.0f + lv - expf(lv) - m*m) * K_KLD;
    }
    for (int i = tid; i < SSIM_BLOCKS; i += 256)
        acc += (double)g_ssim[i] * K_SSIM;
    for (int i = tid; i < STFT_BLOCKS; i += 256)
        acc += (double)g_stft[i] * K_STFT;

    red[tid] = acc;
    __syncthreads();
    #pragma unroll
    for (int s = 128; s > 0; s >>= 1) {
        if (tid < s) red[tid] += red[tid + s];
        __syncthreads();
    }
    if (tid == 0) out[0] = (float)red[0];
}

// ---------------------------------------------------------------------------
extern "C" void kernel_launch(void* const* d_in, const int* in_sizes, int n_in,
                              void* d_out, int out_size)
{
    const float* mean   = (const float*)d_in[0];
    const float* logvar = (const float*)d_in[1];
    const float* xin    = (const float*)d_in[2];
    const float* xout   = (const float*)d_in[3];
    float* out = (float*)d_out;

    ssim_kernel<<<dim3(5, 5, 96), 256>>>(xin, xout);
    stft_kernel<<<dim3(38, 32), 192>>>(xin, xout);
    final_kernel<<<1, 256>>>(mean, logvar, out);
}